// round 1
// baseline (speedup 1.0000x reference)
#include <cuda_runtime.h>
#include <cuda_bf16.h>
#include <cstdint>

// Problem-scale capacities (reference: E=100000, T=1000000, C=64)
#define MAX_E 100000
#define MAX_T 1000000
#define CCH   64

// Scratch (device globals — allocation-free per harness rules)
__device__ float    g_rnorm[MAX_E * 3];
__device__ float    g_a[MAX_T];
__device__ float    g_ex[MAX_T];
__device__ unsigned g_amax[MAX_E];
__device__ float    g_denom[MAX_E];

// Order-preserving float <-> uint key (for atomicMax on float values)
__device__ __forceinline__ unsigned fkey(float f) {
    unsigned u = __float_as_uint(f);
    return (u & 0x80000000u) ? ~u : (u | 0x80000000u);
}
__device__ __forceinline__ float fdecode(unsigned k) {
    unsigned u = (k & 0x80000000u) ? (k & 0x7FFFFFFFu) : ~k;
    return __uint_as_float(u);
}

// ---------------------------------------------------------------------------
// Kernel 0: prep — unit bond directions, zero ft, init segment reducers.
// (negation of r cancels in the src·dst dot product, so skip it)
// ---------------------------------------------------------------------------
__global__ void k_prep(const float* __restrict__ r, float* __restrict__ ft,
                       int E, int n_ft) {
    int i = blockIdx.x * blockDim.x + threadIdx.x;
    if (i < n_ft) ft[i] = 0.0f;
    if (i < E) {
        float x = r[3 * i + 0], y = r[3 * i + 1], z = r[3 * i + 2];
        float inv = 1.0f / sqrtf(x * x + y * y + z * z);
        g_rnorm[3 * i + 0] = x * inv;
        g_rnorm[3 * i + 1] = y * inv;
        g_rnorm[3 * i + 2] = z * inv;
        g_amax[i]  = 0u;      // decodes to -NaN; only read when segment non-empty
        g_denom[i] = 0.0f;
    }
}

// ---------------------------------------------------------------------------
// Kernel 1: per-triplet logits a[t] + segment max over t_dst.
// z_n = cos(n*theta) via rotation recurrence (cos/sin angle-addition),
// theta = arccos(clip(cos_jik)) => cth = clipped cos, sth = sqrt(1-cth^2).
// ---------------------------------------------------------------------------
__global__ void __launch_bounds__(256)
k_pass1(const float* __restrict__ xij, const float* __restrict__ attn,
        const int* __restrict__ tsrc, const int* __restrict__ tdst, int T) {
    __shared__ float sat[CCH];
    if (threadIdx.x < CCH) sat[threadIdx.x] = attn[threadIdx.x];
    __syncthreads();

    int t = blockIdx.x * blockDim.x + threadIdx.x;
    if (t >= T) return;

    int s = tsrc[t], d = tdst[t];

    float rsx = g_rnorm[3 * s + 0], rsy = g_rnorm[3 * s + 1], rsz = g_rnorm[3 * s + 2];
    float rdx = g_rnorm[3 * d + 0], rdy = g_rnorm[3 * d + 1], rdz = g_rnorm[3 * d + 2];
    float cth = rsx * rdx + rsy * rdy + rsz * rdz;
    cth = fminf(fmaxf(cth, -1.0f + 1e-6f), 1.0f - 1e-6f);
    float sth = sqrtf(fmaxf(1.0f - cth * cth, 0.0f));

    const float4* xs = (const float4*)(xij + (size_t)s * CCH);
    const float4* xd = (const float4*)(xij + (size_t)d * CCH);

    float cn = 1.0f, sn = 0.0f;   // cos(0), sin(0)
    float a = 0.0f;

#pragma unroll
    for (int k = 0; k < CCH / 4; k++) {
        float4 A = __ldg(xs + k);
        float4 B = __ldg(xd + k);
        float xv[4] = {A.x + B.x, A.y + B.y, A.z + B.z, A.w + B.w};
#pragma unroll
        for (int j = 0; j < 4; j++) {
            float v = cn + xv[j];                          // z + x_jik
            float e = __fdividef(v, 1.0f + __expf(-v));    // silu
            a = fmaf(e, sat[k * 4 + j], a);
            float c2 = cn * cth - sn * sth;                // rotate by theta
            sn = sn * cth + cn * sth;
            cn = c2;
        }
    }

    g_a[t] = a;
    atomicMax(&g_amax[d], fkey(a));
}

// ---------------------------------------------------------------------------
// Kernel 2: ex = exp(a - amax[dst]); denom = segment_sum(ex)
// ---------------------------------------------------------------------------
__global__ void __launch_bounds__(256)
k_pass2(const int* __restrict__ tdst, int T) {
    int t = blockIdx.x * blockDim.x + threadIdx.x;
    if (t >= T) return;
    int d = tdst[t];
    float amax = fdecode(g_amax[d]);
    float ex = __expf(g_a[t] - amax);
    g_ex[t] = ex;
    atomicAdd(&g_denom[d], ex);
}

// ---------------------------------------------------------------------------
// Kernel 3: alpha = ex/denom[dst]; ft[dst] += alpha * xij[src] (v4 red)
// ---------------------------------------------------------------------------
__global__ void __launch_bounds__(256)
k_pass3(const float* __restrict__ xij, const int* __restrict__ tsrc,
        const int* __restrict__ tdst, float* __restrict__ ft, int T) {
    int t = blockIdx.x * blockDim.x + threadIdx.x;
    if (t >= T) return;
    int s = tsrc[t], d = tdst[t];
    float alpha = __fdividef(g_ex[t], g_denom[d]);

    const float4* xs = (const float4*)(xij + (size_t)s * CCH);
    float* fo = ft + (size_t)d * CCH;

#pragma unroll
    for (int k = 0; k < CCH / 4; k++) {
        float4 A = __ldg(xs + k);
        float m0 = A.x * alpha, m1 = A.y * alpha, m2 = A.z * alpha, m3 = A.w * alpha;
        asm volatile("red.global.add.v4.f32 [%0], {%1, %2, %3, %4};"
                     :: "l"(fo + 4 * k), "f"(m0), "f"(m1), "f"(m2), "f"(m3)
                     : "memory");
    }
}

// ---------------------------------------------------------------------------
extern "C" void kernel_launch(void* const* d_in, const int* in_sizes, int n_in,
                              void* d_out, int out_size) {
    const float* xij  = (const float*)d_in[0];
    const float* r    = (const float*)d_in[1];
    const float* attn = (const float*)d_in[2];
    const int*   tsrc = (const int*)d_in[3];
    const int*   tdst = (const int*)d_in[4];
    float* ft = (float*)d_out;

    int E = in_sizes[1] / 3;
    int T = in_sizes[3];
    int n_ft = out_size;   // E * C

    int prep_n = (n_ft > E) ? n_ft : E;
    k_prep<<<(prep_n + 255) / 256, 256>>>(r, ft, E, n_ft);
    k_pass1<<<(T + 255) / 256, 256>>>(xij, attn, tsrc, tdst, T);
    k_pass2<<<(T + 255) / 256, 256>>>(tdst, T);
    k_pass3<<<(T + 255) / 256, 256>>>(xij, tsrc, tdst, ft, T);
}

// round 2
// speedup vs baseline: 1.4944x; 1.4944x over previous
#include <cuda_runtime.h>
#include <cuda_bf16.h>
#include <cstdint>

#define MAX_E 100000
#define MAX_T 1000000
#define CCH   64
#define SCAN_BLK 512
#define MAX_SCAN_BLOCKS ((MAX_E + SCAN_BLK - 1) / SCAN_BLK)

// Scratch (device globals — allocation-free per harness rules)
__device__ float    g_rnorm[MAX_E * 3];
__device__ unsigned g_cnt[MAX_E];
__device__ unsigned g_off[MAX_E];
__device__ unsigned g_cursor[MAX_E];
__device__ unsigned g_bsum[MAX_SCAN_BLOCKS];
__device__ float    g_ca[MAX_T];     // logits a, CSR(dst)-ordered
__device__ int      g_csrc[MAX_T];   // src edge ids, CSR(dst)-ordered

// ---------------------------------------------------------------------------
// prep: unit bond directions (negation cancels in the dot), zero counters
// ---------------------------------------------------------------------------
__global__ void k_prep(const float* __restrict__ r, int E) {
    int i = blockIdx.x * blockDim.x + threadIdx.x;
    if (i >= E) return;
    float x = r[3 * i + 0], y = r[3 * i + 1], z = r[3 * i + 2];
    float inv = rsqrtf(x * x + y * y + z * z);
    g_rnorm[3 * i + 0] = x * inv;
    g_rnorm[3 * i + 1] = y * inv;
    g_rnorm[3 * i + 2] = z * inv;
    g_cnt[i] = 0u;
    g_cursor[i] = 0u;
}

// ---------------------------------------------------------------------------
// count: per-destination degree histogram
// ---------------------------------------------------------------------------
__global__ void k_count(const int* __restrict__ tdst, int T) {
    int t = blockIdx.x * blockDim.x + threadIdx.x;
    if (t < T) atomicAdd(&g_cnt[tdst[t]], 1u);
}

// ---------------------------------------------------------------------------
// 3-kernel exclusive scan of g_cnt -> g_off
// ---------------------------------------------------------------------------
__global__ void k_scan1(int E) {
    __shared__ unsigned sh[SCAN_BLK];
    int i = blockIdx.x * SCAN_BLK + threadIdx.x;
    unsigned v = (i < E) ? g_cnt[i] : 0u;
    sh[threadIdx.x] = v;
    __syncthreads();
    unsigned incl = v;
    for (int ofs = 1; ofs < SCAN_BLK; ofs <<= 1) {
        unsigned add = (threadIdx.x >= ofs) ? sh[threadIdx.x - ofs] : 0u;
        __syncthreads();
        incl += add;
        sh[threadIdx.x] = incl;
        __syncthreads();
    }
    if (i < E) g_off[i] = incl - v;           // exclusive within block
    if (threadIdx.x == SCAN_BLK - 1) g_bsum[blockIdx.x] = incl;
}

__global__ void k_scan2(int nb) {
    __shared__ unsigned sh[SCAN_BLK];
    unsigned v = (threadIdx.x < nb) ? g_bsum[threadIdx.x] : 0u;
    sh[threadIdx.x] = v;
    __syncthreads();
    unsigned incl = v;
    for (int ofs = 1; ofs < SCAN_BLK; ofs <<= 1) {
        unsigned add = (threadIdx.x >= ofs) ? sh[threadIdx.x - ofs] : 0u;
        __syncthreads();
        incl += add;
        sh[threadIdx.x] = incl;
        __syncthreads();
    }
    if (threadIdx.x < nb) g_bsum[threadIdx.x] = incl - v;  // exclusive
}

__global__ void k_scan3(int E) {
    int i = blockIdx.x * SCAN_BLK + threadIdx.x;
    if (i < E) g_off[i] += g_bsum[blockIdx.x];
}

// ---------------------------------------------------------------------------
// pass1: per-triplet logit a[t]; write (a, src) into CSR(dst) slots.
// Chebyshev T_n(cos th) = cos(n th) via angle-rotation recurrence.
// ---------------------------------------------------------------------------
__global__ void __launch_bounds__(256)
k_pass1(const float* __restrict__ xij, const float* __restrict__ attn,
        const int* __restrict__ tsrc, const int* __restrict__ tdst, int T) {
    __shared__ float sat[CCH];
    if (threadIdx.x < CCH) sat[threadIdx.x] = attn[threadIdx.x];
    __syncthreads();

    int t = blockIdx.x * blockDim.x + threadIdx.x;
    if (t >= T) return;

    int s = tsrc[t], d = tdst[t];

    float rsx = g_rnorm[3 * s + 0], rsy = g_rnorm[3 * s + 1], rsz = g_rnorm[3 * s + 2];
    float rdx = g_rnorm[3 * d + 0], rdy = g_rnorm[3 * d + 1], rdz = g_rnorm[3 * d + 2];
    float cth = rsx * rdx + rsy * rdy + rsz * rdz;
    cth = fminf(fmaxf(cth, -1.0f + 1e-6f), 1.0f - 1e-6f);
    float sth = sqrtf(fmaxf(1.0f - cth * cth, 0.0f));

    const float4* xs = (const float4*)(xij + (size_t)s * CCH);
    const float4* xd = (const float4*)(xij + (size_t)d * CCH);

    float cn = 1.0f, sn = 0.0f;
    float a = 0.0f;

#pragma unroll
    for (int k = 0; k < CCH / 4; k++) {
        float4 A = __ldg(xs + k);
        float4 B = __ldg(xd + k);
        float xv[4] = {A.x + B.x, A.y + B.y, A.z + B.z, A.w + B.w};
#pragma unroll
        for (int j = 0; j < 4; j++) {
            float v = cn + xv[j];                        // z_n + x_jik
            float e = __fdividef(v, 1.0f + __expf(-v));  // silu
            a = fmaf(e, sat[k * 4 + j], a);
            float c2 = cn * cth - sn * sth;              // rotate by theta
            sn = sn * cth + cn * sth;
            cn = c2;
        }
    }

    unsigned pos = g_off[d] + atomicAdd(&g_cursor[d], 1u);
    g_ca[pos] = a;
    g_csrc[pos] = s;
}

// ---------------------------------------------------------------------------
// edge: warp-per-edge fused softmax + aggregate.
// ft[e] = (sum_t ex_t * xij[src_t]) / (sum_t ex_t), ex_t = exp(a_t - max)
// ---------------------------------------------------------------------------
__global__ void __launch_bounds__(256)
k_edge(const float* __restrict__ xij, float* __restrict__ ft, int E) {
    int warp = (blockIdx.x * blockDim.x + threadIdx.x) >> 5;
    int lane = threadIdx.x & 31;
    if (warp >= E) return;

    int base = (int)g_off[warp];
    int deg  = (int)g_cnt[warp];

    // segment max (lanes stride the segment, warp-reduce)
    float m = -3.4e38f;
    for (int i = lane; i < deg; i += 32) m = fmaxf(m, g_ca[base + i]);
#pragma unroll
    for (int o = 16; o > 0; o >>= 1)
        m = fmaxf(m, __shfl_xor_sync(0xFFFFFFFFu, m, o));

    float acc0 = 0.0f, acc1 = 0.0f, denom = 0.0f;

    int i = 0;
    for (; i + 4 <= deg; i += 4) {
        float a0 = g_ca[base + i + 0], a1 = g_ca[base + i + 1];
        float a2 = g_ca[base + i + 2], a3 = g_ca[base + i + 3];
        int s0 = g_csrc[base + i + 0], s1 = g_csrc[base + i + 1];
        int s2 = g_csrc[base + i + 2], s3 = g_csrc[base + i + 3];
        const float* x0 = xij + (size_t)s0 * CCH;
        const float* x1 = xij + (size_t)s1 * CCH;
        const float* x2 = xij + (size_t)s2 * CCH;
        const float* x3 = xij + (size_t)s3 * CCH;
        float x0a = __ldg(x0 + lane), x0b = __ldg(x0 + 32 + lane);
        float x1a = __ldg(x1 + lane), x1b = __ldg(x1 + 32 + lane);
        float x2a = __ldg(x2 + lane), x2b = __ldg(x2 + 32 + lane);
        float x3a = __ldg(x3 + lane), x3b = __ldg(x3 + 32 + lane);
        float e0 = __expf(a0 - m), e1 = __expf(a1 - m);
        float e2 = __expf(a2 - m), e3 = __expf(a3 - m);
        denom += (e0 + e1) + (e2 + e3);
        acc0 = fmaf(e0, x0a, acc0); acc1 = fmaf(e0, x0b, acc1);
        acc0 = fmaf(e1, x1a, acc0); acc1 = fmaf(e1, x1b, acc1);
        acc0 = fmaf(e2, x2a, acc0); acc1 = fmaf(e2, x2b, acc1);
        acc0 = fmaf(e3, x3a, acc0); acc1 = fmaf(e3, x3b, acc1);
    }
    for (; i < deg; i++) {
        float a0 = g_ca[base + i];
        int s0 = g_csrc[base + i];
        const float* x0 = xij + (size_t)s0 * CCH;
        float e0 = __expf(a0 - m);
        denom += e0;
        acc0 = fmaf(e0, __ldg(x0 + lane), acc0);
        acc1 = fmaf(e0, __ldg(x0 + 32 + lane), acc1);
    }

    float inv = (deg > 0) ? __fdividef(1.0f, denom) : 0.0f;
    ft[(size_t)warp * CCH + lane]      = acc0 * inv;
    ft[(size_t)warp * CCH + 32 + lane] = acc1 * inv;
}

// ---------------------------------------------------------------------------
extern "C" void kernel_launch(void* const* d_in, const int* in_sizes, int n_in,
                              void* d_out, int out_size) {
    const float* xij  = (const float*)d_in[0];
    const float* r    = (const float*)d_in[1];
    const float* attn = (const float*)d_in[2];
    const int*   tsrc = (const int*)d_in[3];
    const int*   tdst = (const int*)d_in[4];
    float* ft = (float*)d_out;

    int E = in_sizes[1] / 3;
    int T = in_sizes[3];
    int nb = (E + SCAN_BLK - 1) / SCAN_BLK;

    k_prep <<<(E + 255) / 256, 256>>>(r, E);
    k_count<<<(T + 255) / 256, 256>>>(tdst, T);
    k_scan1<<<nb, SCAN_BLK>>>(E);
    k_scan2<<<1,  SCAN_BLK>>>(nb);
    k_scan3<<<nb, SCAN_BLK>>>(E);
    k_pass1<<<(T + 255) / 256, 256>>>(xij, attn, tsrc, tdst, T);
    k_edge <<<(E * 32 + 255) / 256, 256>>>(xij, ft, E);
}

// round 3
// speedup vs baseline: 2.0344x; 1.3613x over previous
#include <cuda_runtime.h>
#include <cuda_bf16.h>
#include <cstdint>

#define MAX_E 100000
#define MAX_T 1000000
#define CCH   64
#define SCAN_BLK 512
#define MAX_SCAN_BLOCKS ((MAX_E + SCAN_BLK - 1) / SCAN_BLK)
#define TPB1 128   // pass1: triplets per block

// Scratch (device globals — allocation-free per harness rules)
__device__ float4   g_rnorm4[MAX_E];
__device__ unsigned g_cnt[MAX_E];
__device__ unsigned g_off[MAX_E];
__device__ unsigned g_cursor[MAX_E];
__device__ unsigned g_bsum[MAX_SCAN_BLOCKS];
__device__ float    g_ca[MAX_T];     // logits, CSR(dst)-ordered
__device__ int      g_csrc[MAX_T];   // src ids, CSR(dst)-ordered
__device__ int      g_cdst[MAX_T];   // dst ids, CSR(dst)-ordered

// ---------------------------------------------------------------------------
// prep: unit bond dirs (negation cancels in src·dst dot), zero counters
// ---------------------------------------------------------------------------
__global__ void k_prep(const float* __restrict__ r, int E) {
    int i = blockIdx.x * blockDim.x + threadIdx.x;
    if (i >= E) return;
    float x = r[3 * i + 0], y = r[3 * i + 1], z = r[3 * i + 2];
    float inv = rsqrtf(x * x + y * y + z * z);
    g_rnorm4[i] = make_float4(x * inv, y * inv, z * inv, 0.0f);
    g_cnt[i] = 0u;
    g_cursor[i] = 0u;
}

__global__ void k_count(const int* __restrict__ tdst, int T) {
    int t = blockIdx.x * blockDim.x + threadIdx.x;
    if (t < T) atomicAdd(&g_cnt[tdst[t]], 1u);
}

// --------------------------- exclusive scan --------------------------------
__global__ void k_scan1(int E) {
    __shared__ unsigned sh[SCAN_BLK];
    int i = blockIdx.x * SCAN_BLK + threadIdx.x;
    unsigned v = (i < E) ? g_cnt[i] : 0u;
    sh[threadIdx.x] = v;
    __syncthreads();
    unsigned incl = v;
    for (int ofs = 1; ofs < SCAN_BLK; ofs <<= 1) {
        unsigned add = (threadIdx.x >= ofs) ? sh[threadIdx.x - ofs] : 0u;
        __syncthreads();
        incl += add;
        sh[threadIdx.x] = incl;
        __syncthreads();
    }
    if (i < E) g_off[i] = incl - v;
    if (threadIdx.x == SCAN_BLK - 1) g_bsum[blockIdx.x] = incl;
}

__global__ void k_scan2(int nb) {
    __shared__ unsigned sh[SCAN_BLK];
    unsigned v = (threadIdx.x < nb) ? g_bsum[threadIdx.x] : 0u;
    sh[threadIdx.x] = v;
    __syncthreads();
    unsigned incl = v;
    for (int ofs = 1; ofs < SCAN_BLK; ofs <<= 1) {
        unsigned add = (threadIdx.x >= ofs) ? sh[threadIdx.x - ofs] : 0u;
        __syncthreads();
        incl += add;
        sh[threadIdx.x] = incl;
        __syncthreads();
    }
    if (threadIdx.x < nb) g_bsum[threadIdx.x] = incl - v;
}

__global__ void k_scan3(int E) {
    int i = blockIdx.x * SCAN_BLK + threadIdx.x;
    if (i < E) g_off[i] += g_bsum[blockIdx.x];
}

// ---------------------------------------------------------------------------
// perm: scatter triplets into CSR(dst) order
// ---------------------------------------------------------------------------
__global__ void k_perm(const int* __restrict__ tsrc, const int* __restrict__ tdst, int T) {
    int t = blockIdx.x * blockDim.x + threadIdx.x;
    if (t >= T) return;
    int d = tdst[t];
    unsigned pos = g_off[d] + atomicAdd(&g_cursor[d], 1u);
    g_csrc[pos] = tsrc[t];
    g_cdst[pos] = d;
}

// ---------------------------------------------------------------------------
// pass1: logits in CSR order.
//  - xij[src] rows staged to smem via warp-cooperative coalesced loads
//    (padded stride 65 words -> conflict-free LDS in compute phase)
//  - xij[dst] read directly: CSR adjacency => ~4 distinct rows/warp, L1-hits
//  - Chebyshev via 3-term recurrence: T_{n+1} = 2c*T_n - T_{n-1} (1 FMA/ch)
// ---------------------------------------------------------------------------
__global__ void __launch_bounds__(TPB1)
k_pass1(const float* __restrict__ xij, const float* __restrict__ attn, int T) {
    __shared__ float sx[TPB1 * 65];
    __shared__ float sat[CCH];
    int tid = threadIdx.x;
    int base = blockIdx.x * TPB1;
    if (tid < CCH) sat[tid] = attn[tid];

    // cooperative gather of src rows (1 row per warp per step, coalesced)
    int lane = tid & 31, w = tid >> 5;
    for (int j = w; j < TPB1; j += TPB1 / 32) {
        int t = base + j;
        if (t < T) {
            int s = g_csrc[t];
            float2 v = __ldg((const float2*)(xij + (size_t)s * CCH) + lane);
            sx[j * 65 + 2 * lane]     = v.x;
            sx[j * 65 + 2 * lane + 1] = v.y;
        }
    }
    __syncthreads();

    int t = base + tid;
    if (t >= T) return;
    int s = g_csrc[t], d = g_cdst[t];

    float4 rs = __ldg(&g_rnorm4[s]);
    float4 rd = __ldg(&g_rnorm4[d]);
    float cth = rs.x * rd.x + rs.y * rd.y + rs.z * rd.z;
    cth = fminf(fmaxf(cth, -1.0f + 1e-6f), 1.0f - 1e-6f);
    float c2 = 2.0f * cth;
    float zp = cth, zc = 1.0f;   // T_{-1}=cos(-th)=cth, T_0=1

    const float4* xd = (const float4*)(xij + (size_t)d * CCH);
    const float* row = &sx[tid * 65];
    float a = 0.0f;

#pragma unroll
    for (int k = 0; k < CCH / 4; k++) {
        float4 D = __ldg(xd + k);
        float dv[4] = {D.x, D.y, D.z, D.w};
#pragma unroll
        for (int j = 0; j < 4; j++) {
            int c = 4 * k + j;
            float v = zc + row[c] + dv[j];
            float e = __fdividef(v, 1.0f + __expf(-v));   // silu
            a = fmaf(e, sat[c], a);
            float zn = fmaf(c2, zc, -zp);                 // Chebyshev step
            zp = zc; zc = zn;
        }
    }
    g_ca[t] = a;   // coalesced (CSR order)
}

// ---------------------------------------------------------------------------
// edge: warp-per-edge fused softmax + aggregate.
// ---------------------------------------------------------------------------
__global__ void __launch_bounds__(256)
k_edge(const float* __restrict__ xij, float* __restrict__ ft, int E) {
    int warp = (blockIdx.x * blockDim.x + threadIdx.x) >> 5;
    int lane = threadIdx.x & 31;
    if (warp >= E) return;

    int base = (int)g_off[warp];
    int deg  = (int)g_cnt[warp];

    float m = -3.4e38f;
    for (int i = lane; i < deg; i += 32) m = fmaxf(m, g_ca[base + i]);
#pragma unroll
    for (int o = 16; o > 0; o >>= 1)
        m = fmaxf(m, __shfl_xor_sync(0xFFFFFFFFu, m, o));

    float acc0 = 0.0f, acc1 = 0.0f, denom = 0.0f;

    int i = 0;
    for (; i + 4 <= deg; i += 4) {
        float a0 = g_ca[base + i + 0], a1 = g_ca[base + i + 1];
        float a2 = g_ca[base + i + 2], a3 = g_ca[base + i + 3];
        int s0 = g_csrc[base + i + 0], s1 = g_csrc[base + i + 1];
        int s2 = g_csrc[base + i + 2], s3 = g_csrc[base + i + 3];
        const float* x0 = xij + (size_t)s0 * CCH;
        const float* x1 = xij + (size_t)s1 * CCH;
        const float* x2 = xij + (size_t)s2 * CCH;
        const float* x3 = xij + (size_t)s3 * CCH;
        float x0a = __ldg(x0 + lane), x0b = __ldg(x0 + 32 + lane);
        float x1a = __ldg(x1 + lane), x1b = __ldg(x1 + 32 + lane);
        float x2a = __ldg(x2 + lane), x2b = __ldg(x2 + 32 + lane);
        float x3a = __ldg(x3 + lane), x3b = __ldg(x3 + 32 + lane);
        float e0 = __expf(a0 - m), e1 = __expf(a1 - m);
        float e2 = __expf(a2 - m), e3 = __expf(a3 - m);
        denom += (e0 + e1) + (e2 + e3);
        acc0 = fmaf(e0, x0a, acc0); acc1 = fmaf(e0, x0b, acc1);
        acc0 = fmaf(e1, x1a, acc0); acc1 = fmaf(e1, x1b, acc1);
        acc0 = fmaf(e2, x2a, acc0); acc1 = fmaf(e2, x2b, acc1);
        acc0 = fmaf(e3, x3a, acc0); acc1 = fmaf(e3, x3b, acc1);
    }
    for (; i < deg; i++) {
        float a0 = g_ca[base + i];
        int s0 = g_csrc[base + i];
        const float* x0 = xij + (size_t)s0 * CCH;
        float e0 = __expf(a0 - m);
        denom += e0;
        acc0 = fmaf(e0, __ldg(x0 + lane), acc0);
        acc1 = fmaf(e0, __ldg(x0 + 32 + lane), acc1);
    }

    float inv = (deg > 0) ? __fdividef(1.0f, denom) : 0.0f;
    ft[(size_t)warp * CCH + lane]      = acc0 * inv;
    ft[(size_t)warp * CCH + 32 + lane] = acc1 * inv;
}

// ---------------------------------------------------------------------------
extern "C" void kernel_launch(void* const* d_in, const int* in_sizes, int n_in,
                              void* d_out, int out_size) {
    const float* xij  = (const float*)d_in[0];
    const float* r    = (const float*)d_in[1];
    const float* attn = (const float*)d_in[2];
    const int*   tsrc = (const int*)d_in[3];
    const int*   tdst = (const int*)d_in[4];
    float* ft = (float*)d_out;

    int E = in_sizes[1] / 3;
    int T = in_sizes[3];
    int nb = (E + SCAN_BLK - 1) / SCAN_BLK;

    k_prep <<<(E + 255) / 256, 256>>>(r, E);
    k_count<<<(T + 255) / 256, 256>>>(tdst, T);
    k_scan1<<<nb, SCAN_BLK>>>(E);
    k_scan2<<<1,  SCAN_BLK>>>(nb);
    k_scan3<<<nb, SCAN_BLK>>>(E);
    k_perm <<<(T + 255) / 256, 256>>>(tsrc, tdst, T);
    k_pass1<<<(T + TPB1 - 1) / TPB1, TPB1>>>(xij, attn, T);
    k_edge <<<(E * 32 + 255) / 256, 256>>>(xij, ft, E);
}